// round 14
// baseline (speedup 1.0000x reference)
#include <cuda_runtime.h>
#include <cuda_bf16.h>
#include <cstdint>

// Shapes (fixed): joint [B=1024, D=1024], conf [K=256, D=1024], prior [K,1],
// Wq [D, P=768], Wk [D, P=768], out [B, D]. All fp32 in global.
//
// Dataflow (bf16 HMMA mma.sync, fp32 accum; split-K = 4 on skinny GEMMs):
//   conv:  joint_bf, conf_bf, Wq_bf, Wk_bf        (one fused kernel)
//   G1(NN, splitK=4): part = conf_bf @ Wk_bf      (K=1024,Kc=256) -> fp32 partials
//        reduce(4) -> Kmat_bf [256,768]
//   G2(NT, splitK=4): part = Kmat @ Wq_bf^T       (K=768, Kc=192) -> fp32 partials
//        reduce(4) -> W2T_bf [256,1024]
//   G3(NT, splitK=4): part = joint_bf @ W2T^T     (K=1024,Kc=256) -> fp32 partials
//   softmax (fused: sum 4 partials, *1/32, softmax, *prior) -> attn_bf [1024,256]
//   G4(NN): out = attn_bf @ conf_bf + joint       (K=256)  -> f32
//
// GEMM core: 64x64 CTA tile, 4 warps (2x2, 32x32 each), BK=64, cp.async
// double-buffered smem + REGISTER fragment double-buffering (prefetch ks+1
// fragments before ks MMAs) to overlap ldmatrix latency with HMMA issue.

#define BB 1024
#define KK 256
#define DD 1024
#define PP 768
#define SPLITS 4

// ---------------- scratch (device globals; no allocation allowed) ----------
__device__ __align__(16) __nv_bfloat16 g_joint_bf[BB * DD];
__device__ __align__(16) __nv_bfloat16 g_conf_bf[KK * DD];
__device__ __align__(16) __nv_bfloat16 g_Wq_bf[DD * PP];
__device__ __align__(16) __nv_bfloat16 g_Wk_bf[DD * PP];
__device__ __align__(16) __nv_bfloat16 g_Kmat_bf[KK * PP];
__device__ __align__(16) __nv_bfloat16 g_W2T_bf[KK * DD];
__device__ __align__(16) __nv_bfloat16 g_attn_bf[BB * KK];
__device__ __align__(16) float         g_part[SPLITS * BB * KK];  // 4 MB, reused

// ---------------- baseline-PTX helpers --------------------------------------
__device__ __forceinline__ uint32_t smem_u32(const void* p) {
    uint32_t a;
    asm("{ .reg .u64 t; cvta.to.shared.u64 t, %1; cvt.u32.u64 %0, t; }"
        : "=r"(a) : "l"(p));
    return a;
}
__device__ __forceinline__ void cp_async16(uint32_t dst, const void* src) {
    asm volatile("cp.async.cg.shared.global [%0], [%1], 16;"
                 :: "r"(dst), "l"(src) : "memory");
}
__device__ __forceinline__ void cp_commit() {
    asm volatile("cp.async.commit_group;" ::: "memory");
}
__device__ __forceinline__ void cp_wait1() {
    asm volatile("cp.async.wait_group 1;" ::: "memory");
}
__device__ __forceinline__ void cp_wait0() {
    asm volatile("cp.async.wait_group 0;" ::: "memory");
}
__device__ __forceinline__ void ldmatrix_x4(uint32_t* r, uint32_t addr) {
    asm volatile("ldmatrix.sync.aligned.m8n8.x4.shared.b16 {%0,%1,%2,%3}, [%4];"
                 : "=r"(r[0]), "=r"(r[1]), "=r"(r[2]), "=r"(r[3]) : "r"(addr));
}
__device__ __forceinline__ void ldmatrix_x4_trans(uint32_t* r, uint32_t addr) {
    asm volatile("ldmatrix.sync.aligned.m8n8.x4.trans.shared.b16 {%0,%1,%2,%3}, [%4];"
                 : "=r"(r[0]), "=r"(r[1]), "=r"(r[2]), "=r"(r[3]) : "r"(addr));
}
__device__ __forceinline__ void mma_bf16(float* c, const uint32_t* a,
                                         uint32_t b0, uint32_t b1) {
    asm volatile(
        "mma.sync.aligned.m16n8k16.row.col.f32.bf16.bf16.f32 "
        "{%0,%1,%2,%3}, {%4,%5,%6,%7}, {%8,%9}, {%0,%1,%2,%3};"
        : "+f"(c[0]), "+f"(c[1]), "+f"(c[2]), "+f"(c[3])
        : "r"(a[0]), "r"(a[1]), "r"(a[2]), "r"(a[3]), "r"(b0), "r"(b1));
}
__device__ __forceinline__ uint32_t sw128(uint32_t off) {
    return off ^ ((off >> 3) & 0x70);
}

// ---------------- fused fp32 -> bf16 conversion (all 4 inputs) --------------
#define N4_JOINT  (BB * DD / 4)
#define N4_CONF   (KK * DD / 4)
#define N4_W      (DD * PP / 4)
#define N4_TOTAL  (N4_JOINT + N4_CONF + 2 * N4_W)

__global__ __launch_bounds__(256) void conv_all(
    const float* __restrict__ joint, const float* __restrict__ conf,
    const float* __restrict__ wq, const float* __restrict__ wk,
    __nv_bfloat16* __restrict__ jb, __nv_bfloat16* __restrict__ cb,
    __nv_bfloat16* __restrict__ qb, __nv_bfloat16* __restrict__ kb)
{
    int i = blockIdx.x * blockDim.x + threadIdx.x;
    const float* src;
    __nv_bfloat16* dst;
    int off;
    if (i < N4_JOINT)                       { src = joint; dst = jb; off = i; }
    else if (i < N4_JOINT + N4_CONF)        { src = conf;  dst = cb; off = i - N4_JOINT; }
    else if (i < N4_JOINT + N4_CONF + N4_W) { src = wq;    dst = qb; off = i - N4_JOINT - N4_CONF; }
    else if (i < N4_TOTAL)                  { src = wk;    dst = kb; off = i - N4_JOINT - N4_CONF - N4_W; }
    else return;
    float4 v = ((const float4*)src)[off];
    __nv_bfloat162 a = __floats2bfloat162_rn(v.x, v.y);
    __nv_bfloat162 b = __floats2bfloat162_rn(v.z, v.w);
    uint2 u;
    u.x = *reinterpret_cast<uint32_t*>(&a);
    u.y = *reinterpret_cast<uint32_t*>(&b);
    ((uint2*)dst)[off] = u;
}

// ------- reduce SPLITS fp32 partials -> bf16 ---------------------------------
__global__ __launch_bounds__(256) void reduce_bf16(
    const float* __restrict__ part, __nv_bfloat16* __restrict__ out,
    int n4, int stride4)
{
    int i = blockIdx.x * blockDim.x + threadIdx.x;
    if (i >= n4) return;
    float4 s = ((const float4*)part)[i];
    #pragma unroll
    for (int sp = 1; sp < SPLITS; ++sp) {
        float4 v = ((const float4*)part)[i + sp * stride4];
        s.x += v.x; s.y += v.y; s.z += v.z; s.w += v.w;
    }
    __nv_bfloat162 a = __floats2bfloat162_rn(s.x, s.y);
    __nv_bfloat162 b = __floats2bfloat162_rn(s.z, s.w);
    uint2 u;
    u.x = *reinterpret_cast<uint32_t*>(&a);
    u.y = *reinterpret_cast<uint32_t*>(&b);
    ((uint2*)out)[i] = u;
}

// ------- softmax: sum SPLITS S-partials, *1/32, softmax, *prior -> bf16 ------
__global__ __launch_bounds__(256) void softmax_bf16(
    const float* __restrict__ Sp, const float* __restrict__ prior,
    __nv_bfloat16* __restrict__ A)
{
    const int STR4 = BB * KK / 4;   // float4 stride between splits
    int w = threadIdx.x >> 5, lid = threadIdx.x & 31;
    int row = blockIdx.x * 8 + w;
    int base4 = row * (KK / 4);
    float4 v0 = ((const float4*)Sp)[base4 + lid];
    float4 v1 = ((const float4*)Sp)[base4 + lid + 32];
    #pragma unroll
    for (int sp = 1; sp < SPLITS; ++sp) {
        float4 a = ((const float4*)Sp)[base4 + lid + sp * STR4];
        float4 b = ((const float4*)Sp)[base4 + lid + 32 + sp * STR4];
        v0.x += a.x; v0.y += a.y; v0.z += a.z; v0.w += a.w;
        v1.x += b.x; v1.y += b.y; v1.z += b.z; v1.w += b.w;
    }
    const float alpha = 0.03125f;
    float e[8] = {v0.x * alpha, v0.y * alpha, v0.z * alpha, v0.w * alpha,
                  v1.x * alpha, v1.y * alpha, v1.z * alpha, v1.w * alpha};
    float mx = e[0];
    #pragma unroll
    for (int i = 1; i < 8; i++) mx = fmaxf(mx, e[i]);
    #pragma unroll
    for (int o = 16; o; o >>= 1) mx = fmaxf(mx, __shfl_xor_sync(~0u, mx, o));
    float s = 0.f;
    #pragma unroll
    for (int i = 0; i < 8; i++) { e[i] = __expf(e[i] - mx); s += e[i]; }
    #pragma unroll
    for (int o = 16; o; o >>= 1) s += __shfl_xor_sync(~0u, s, o);
    float inv = 1.0f / s;
    float4 p0 = ((const float4*)prior)[lid];
    float4 p1 = ((const float4*)prior)[lid + 32];
    __nv_bfloat162 b01 = __floats2bfloat162_rn(e[0] * inv * p0.x, e[1] * inv * p0.y);
    __nv_bfloat162 b23 = __floats2bfloat162_rn(e[2] * inv * p0.z, e[3] * inv * p0.w);
    __nv_bfloat162 b45 = __floats2bfloat162_rn(e[4] * inv * p1.x, e[5] * inv * p1.y);
    __nv_bfloat162 b67 = __floats2bfloat162_rn(e[6] * inv * p1.z, e[7] * inv * p1.w);
    uint2 lo = make_uint2(*reinterpret_cast<uint32_t*>(&b01), *reinterpret_cast<uint32_t*>(&b23));
    uint2 hi = make_uint2(*reinterpret_cast<uint32_t*>(&b45), *reinterpret_cast<uint32_t*>(&b67));
    *(uint2*)(A + (size_t)row * KK + lid * 4)       = lo;
    *(uint2*)(A + (size_t)row * KK + 128 + lid * 4) = hi;
}

// ---------------- HMMA GEMM core (64x64 tile, 4 warps, BK=64) ---------------
#define TM 64
#define TN 64
#define TKB 128
#define A_BYTES (TM * TKB)
#define STAGE_BYTES (2 * A_BYTES)

// SPLIT: K partitioned by blockIdx.z (Kc per split); fp32 partials at
// Cout + z*M*N. Non-split MODE 2 = f32 out + resid (G4).
template <int BNN, int SPLIT, int MODE>
__global__ __launch_bounds__(128, 5) void gemm_hmma(
    const __nv_bfloat16* __restrict__ A, const __nv_bfloat16* __restrict__ B,
    void* __restrict__ Cout, const float* __restrict__ resid,
    int Ntot, int Mtot, int K, int Kc)
{
    extern __shared__ char dsm_raw[];
    char* dsm = (char*)(((uintptr_t)dsm_raw + 1023) & ~(uintptr_t)1023);
    const uint32_t smem_base = smem_u32(dsm);

    const int tid = threadIdx.x;
    const int wid = tid >> 5;
    const int lid = tid & 31;
    const int wm = (wid >> 1) * 32;
    const int wn = (wid & 1) * 32;

    const int row0 = blockIdx.y * TM;
    const int col0 = blockIdx.x * TN;
    const int Koff = SPLIT ? blockIdx.z * Kc : 0;
    const int nk = (SPLIT ? Kc : K) >> 6;

    const char* Abase = (const char*)A;
    const char* Bbase = (const char*)B;

    float acc[2][4][4] = {};

    auto load_stage = [&](int s, int it) {
        const uint32_t sA = smem_base + s * STAGE_BYTES;
        const uint32_t sB = sA + A_BYTES;
        #pragma unroll
        for (int i = 0; i < 4; i++) {
            int ci = tid + i * 128;
            int r = ci >> 3, c16 = ci & 7;
            size_t gb = ((size_t)(row0 + r) * K + Koff + it * 64) * 2 + c16 * 16;
            uint32_t off = r * TKB + c16 * 16;
            cp_async16(sA + sw128(off), Abase + gb);
        }
        #pragma unroll
        for (int i = 0; i < 4; i++) {
            int ci = tid + i * 128;
            int r = ci >> 3, c16 = ci & 7;
            size_t gb;
            if (BNN)
                gb = ((size_t)(Koff + it * 64 + r) * Ntot + col0) * 2 + c16 * 16;
            else
                gb = ((size_t)(col0 + r) * K + Koff + it * 64) * 2 + c16 * 16;
            uint32_t off = r * TKB + c16 * 16;
            cp_async16(sB + sw128(off), Bbase + gb);
        }
        cp_commit();
    };

    // Fragment loaders for k-slice ks (0..3) from stage base sA/sB.
    auto load_afrags = [&](uint32_t sA, int ks, uint32_t afr[2][4]) {
        #pragma unroll
        for (int mi = 0; mi < 2; ++mi) {
            int row = wm + mi * 16 + (lid & 15);
            uint32_t off = row * TKB + ks * 32 + (lid >> 4) * 16;
            ldmatrix_x4(afr[mi], sA + sw128(off));
        }
    };
    auto load_bfrags = [&](uint32_t sB, int ks, uint32_t bfr[2][4]) {
        #pragma unroll
        for (int np = 0; np < 2; ++np) {
            if (BNN) {
                int k = ks * 16 + ((lid >> 3) & 1) * 8 + (lid & 7);
                int n = wn + np * 16 + (lid >> 4) * 8;
                uint32_t off = k * TKB + n * 2;
                ldmatrix_x4_trans(bfr[np], sB + sw128(off));
            } else {
                int row = wn + np * 16 + ((lid >> 4) << 3) + (lid & 7);
                uint32_t off = row * TKB + ks * 32 + ((lid >> 3) & 1) * 16;
                ldmatrix_x4(bfr[np], sB + sw128(off));
            }
        }
    };

    load_stage(0, 0);

    for (int it = 0; it < nk; ++it) {
        if (it + 1 < nk) { load_stage((it + 1) & 1, it + 1); cp_wait1(); }
        else             { cp_wait0(); }
        __syncthreads();

        const uint32_t sA = smem_base + (it & 1) * STAGE_BYTES;
        const uint32_t sB = sA + A_BYTES;

        // Register double-buffered fragments: prefetch ks+1 before ks MMAs.
        uint32_t afr[2][2][4], bfr[2][2][4];
        load_afrags(sA, 0, afr[0]);
        load_bfrags(sB, 0, bfr[0]);

        #pragma unroll
        for (int ks = 0; ks < 4; ++ks) {
            const int cur = ks & 1, nxt = cur ^ 1;
            if (ks < 3) {
                load_afrags(sA, ks + 1, afr[nxt]);
                load_bfrags(sB, ks + 1, bfr[nxt]);
            }
            #pragma unroll
            for (int mi = 0; mi < 2; ++mi)
                #pragma unroll
                for (int ni = 0; ni < 4; ++ni)
                    mma_bf16(acc[mi][ni], afr[cur][mi],
                             bfr[cur][ni >> 1][(ni & 1) * 2],
                             bfr[cur][ni >> 1][(ni & 1) * 2 + 1]);
        }
        __syncthreads();
    }

    const int group = lid >> 2;
    const int tc = (lid & 3) * 2;
    float* opart = (float*)Cout + (SPLIT ? (size_t)blockIdx.z * Mtot * Ntot : 0);
    #pragma unroll
    for (int mi = 0; mi < 2; ++mi) {
        #pragma unroll
        for (int ni = 0; ni < 4; ++ni) {
            int r = row0 + wm + mi * 16 + group;
            int c = col0 + wn + ni * 8 + tc;
            float* cc = acc[mi][ni];
            if (SPLIT) {
                *(float2*)(opart + (size_t)r * Ntot + c) = make_float2(cc[0], cc[1]);
                *(float2*)(opart + (size_t)(r + 8) * Ntot + c) = make_float2(cc[2], cc[3]);
            } else if (MODE == 2) {
                float* o = (float*)Cout;
                float2 j0 = *(const float2*)(resid + (size_t)r * Ntot + c);
                float2 j1 = *(const float2*)(resid + (size_t)(r + 8) * Ntot + c);
                *(float2*)(o + (size_t)r * Ntot + c) = make_float2(cc[0] + j0.x, cc[1] + j0.y);
                *(float2*)(o + (size_t)(r + 8) * Ntot + c) = make_float2(cc[2] + j1.x, cc[3] + j1.y);
            }
        }
    }
}

// ---------------- host ------------------------------------------------------
extern "C" void kernel_launch(void* const* d_in, const int* in_sizes, int n_in,
                              void* d_out, int out_size)
{
    const float* joint = (const float*)d_in[0];
    const float* conf  = (const float*)d_in[1];
    const float* prior = (const float*)d_in[2];
    const float* Wq    = (const float*)d_in[3];
    const float* Wk    = (const float*)d_in[4];
    float* out = (float*)d_out;

    __nv_bfloat16 *joint_bf, *conf_bf, *Wq_bf, *Wk_bf, *Kmat_bf, *W2T_bf, *attn_bf;
    float* part;
    cudaGetSymbolAddress((void**)&joint_bf, g_joint_bf);
    cudaGetSymbolAddress((void**)&conf_bf,  g_conf_bf);
    cudaGetSymbolAddress((void**)&Wq_bf,    g_Wq_bf);
    cudaGetSymbolAddress((void**)&Wk_bf,    g_Wk_bf);
    cudaGetSymbolAddress((void**)&Kmat_bf,  g_Kmat_bf);
    cudaGetSymbolAddress((void**)&W2T_bf,   g_W2T_bf);
    cudaGetSymbolAddress((void**)&attn_bf,  g_attn_bf);
    cudaGetSymbolAddress((void**)&part,     g_part);

    const int smem_bytes = 2 * STAGE_BYTES + 1024;   // 33 KB
    cudaFuncSetAttribute((const void*)gemm_hmma<1, 1, 0>, cudaFuncAttributeMaxDynamicSharedMemorySize, smem_bytes);
    cudaFuncSetAttribute((const void*)gemm_hmma<0, 1, 0>, cudaFuncAttributeMaxDynamicSharedMemorySize, smem_bytes);
    cudaFuncSetAttribute((const void*)gemm_hmma<1, 0, 2>, cudaFuncAttributeMaxDynamicSharedMemorySize, smem_bytes);

    // fused conversions
    conv_all<<<(N4_TOTAL + 255) / 256, 256>>>(joint, conf, Wq, Wk,
                                              joint_bf, conf_bf, Wq_bf, Wk_bf);
    // G1 (NN, split-K 4): part = conf_bf @ Wk_bf  (K=1024, Kc=256) -> 192 CTAs
    gemm_hmma<1, 1, 0><<<dim3(PP / TN, KK / TM, SPLITS), 128, smem_bytes>>>(
        conf_bf, Wk_bf, part, nullptr, PP, KK, DD, DD / SPLITS);
    reduce_bf16<<<(KK * PP / 4 + 255) / 256, 256>>>(part, Kmat_bf, KK * PP / 4,
                                                    KK * PP / 4);
    // G2 (NT, split-K 4): part = Kmat @ Wq_bf^T  (K=768, Kc=192) -> 256 CTAs
    gemm_hmma<0, 1, 0><<<dim3(DD / TN, KK / TM, SPLITS), 128, smem_bytes>>>(
        Kmat_bf, Wq_bf, part, nullptr, DD, KK, PP, PP / SPLITS);
    reduce_bf16<<<(KK * DD / 4 + 255) / 256, 256>>>(part, W2T_bf, KK * DD / 4,
                                                    KK * DD / 4);
    // G3 (NT, split-K 4): part = joint_bf @ W2T^T  (K=1024, Kc=256) -> 256 CTAs
    gemm_hmma<0, 1, 0><<<dim3(KK / TN, BB / TM, SPLITS), 128, smem_bytes>>>(
        joint_bf, W2T_bf, part, nullptr, KK, BB, DD, DD / SPLITS);
    // softmax: fused 4-way partial reduce + *1/32 + softmax + *prior -> attn
    softmax_bf16<<<BB / 8, 256>>>(part, prior, attn_bf);
    // G4 (NN): out = attn_bf @ conf_bf + joint  (K=256) -> 256 CTAs
    gemm_hmma<1, 0, 2><<<dim3(DD / TN, BB / TM, 1), 128, smem_bytes>>>(
        attn_bf, conf_bf, out, joint, DD, BB, KK, KK);
}

// round 15
// speedup vs baseline: 1.2591x; 1.2591x over previous
#include <cuda_runtime.h>
#include <cuda_bf16.h>
#include <cstdint>

// Shapes (fixed): joint [B=1024, D=1024], conf [K=256, D=1024], prior [K,1],
// Wq [D, P=768], Wk [D, P=768], out [B, D]. All fp32 in global.
//
// Dataflow (bf16 HMMA mma.sync, fp32 accum; split-K = 4 on skinny GEMMs):
//   conv:  joint_bf, conf_bf, Wq_bf, Wk_bf        (one fused kernel)
//   G1(NN, splitK=4): part = conf_bf @ Wk_bf      (K=1024,Kc=256) -> fp32 partials
//        reduce(4) -> Kmat_bf [256,768]
//   G2(NT, splitK=4): part = Kmat @ Wq_bf^T       (K=768, Kc=192) -> fp32 partials
//        reduce(4) -> W2T_bf [256,1024]
//   G3(NT, splitK=4): part = joint_bf @ W2T^T     (K=1024,Kc=256) -> fp32 partials
//   softmax (fused: sum 4 partials, *1/32, softmax, *prior) -> attn_bf [1024,256]
//   G4(NN): out = attn_bf @ conf_bf + joint       (K=256)  -> f32
//
// GEMM core: 64x64 CTA tile, 8 warps (2x4), warp tile 32x16, BK=64,
// cp.async double-buffered smem. Small warp tiles double warp count
// (latency hiding) at modest MMA:ldmatrix ratio cost.

#define BB 1024
#define KK 256
#define DD 1024
#define PP 768
#define SPLITS 4

// ---------------- scratch (device globals; no allocation allowed) ----------
__device__ __align__(16) __nv_bfloat16 g_joint_bf[BB * DD];
__device__ __align__(16) __nv_bfloat16 g_conf_bf[KK * DD];
__device__ __align__(16) __nv_bfloat16 g_Wq_bf[DD * PP];
__device__ __align__(16) __nv_bfloat16 g_Wk_bf[DD * PP];
__device__ __align__(16) __nv_bfloat16 g_Kmat_bf[KK * PP];
__device__ __align__(16) __nv_bfloat16 g_W2T_bf[KK * DD];
__device__ __align__(16) __nv_bfloat16 g_attn_bf[BB * KK];
__device__ __align__(16) float         g_part[SPLITS * BB * KK];  // 4 MB, reused

// ---------------- baseline-PTX helpers --------------------------------------
__device__ __forceinline__ uint32_t smem_u32(const void* p) {
    uint32_t a;
    asm("{ .reg .u64 t; cvta.to.shared.u64 t, %1; cvt.u32.u64 %0, t; }"
        : "=r"(a) : "l"(p));
    return a;
}
__device__ __forceinline__ void cp_async16(uint32_t dst, const void* src) {
    asm volatile("cp.async.cg.shared.global [%0], [%1], 16;"
                 :: "r"(dst), "l"(src) : "memory");
}
__device__ __forceinline__ void cp_commit() {
    asm volatile("cp.async.commit_group;" ::: "memory");
}
__device__ __forceinline__ void cp_wait1() {
    asm volatile("cp.async.wait_group 1;" ::: "memory");
}
__device__ __forceinline__ void cp_wait0() {
    asm volatile("cp.async.wait_group 0;" ::: "memory");
}
__device__ __forceinline__ void ldmatrix_x4(uint32_t* r, uint32_t addr) {
    asm volatile("ldmatrix.sync.aligned.m8n8.x4.shared.b16 {%0,%1,%2,%3}, [%4];"
                 : "=r"(r[0]), "=r"(r[1]), "=r"(r[2]), "=r"(r[3]) : "r"(addr));
}
__device__ __forceinline__ void ldmatrix_x4_trans(uint32_t* r, uint32_t addr) {
    asm volatile("ldmatrix.sync.aligned.m8n8.x4.trans.shared.b16 {%0,%1,%2,%3}, [%4];"
                 : "=r"(r[0]), "=r"(r[1]), "=r"(r[2]), "=r"(r[3]) : "r"(addr));
}
__device__ __forceinline__ void mma_bf16(float* c, const uint32_t* a,
                                         uint32_t b0, uint32_t b1) {
    asm volatile(
        "mma.sync.aligned.m16n8k16.row.col.f32.bf16.bf16.f32 "
        "{%0,%1,%2,%3}, {%4,%5,%6,%7}, {%8,%9}, {%0,%1,%2,%3};"
        : "+f"(c[0]), "+f"(c[1]), "+f"(c[2]), "+f"(c[3])
        : "r"(a[0]), "r"(a[1]), "r"(a[2]), "r"(a[3]), "r"(b0), "r"(b1));
}
__device__ __forceinline__ uint32_t sw128(uint32_t off) {
    return off ^ ((off >> 3) & 0x70);
}

// ---------------- fused fp32 -> bf16 conversion (all 4 inputs) --------------
#define N4_JOINT  (BB * DD / 4)
#define N4_CONF   (KK * DD / 4)
#define N4_W      (DD * PP / 4)
#define N4_TOTAL  (N4_JOINT + N4_CONF + 2 * N4_W)

__global__ __launch_bounds__(256) void conv_all(
    const float* __restrict__ joint, const float* __restrict__ conf,
    const float* __restrict__ wq, const float* __restrict__ wk,
    __nv_bfloat16* __restrict__ jb, __nv_bfloat16* __restrict__ cb,
    __nv_bfloat16* __restrict__ qb, __nv_bfloat16* __restrict__ kb)
{
    int i = blockIdx.x * blockDim.x + threadIdx.x;
    const float* src;
    __nv_bfloat16* dst;
    int off;
    if (i < N4_JOINT)                       { src = joint; dst = jb; off = i; }
    else if (i < N4_JOINT + N4_CONF)        { src = conf;  dst = cb; off = i - N4_JOINT; }
    else if (i < N4_JOINT + N4_CONF + N4_W) { src = wq;    dst = qb; off = i - N4_JOINT - N4_CONF; }
    else if (i < N4_TOTAL)                  { src = wk;    dst = kb; off = i - N4_JOINT - N4_CONF - N4_W; }
    else return;
    float4 v = ((const float4*)src)[off];
    __nv_bfloat162 a = __floats2bfloat162_rn(v.x, v.y);
    __nv_bfloat162 b = __floats2bfloat162_rn(v.z, v.w);
    uint2 u;
    u.x = *reinterpret_cast<uint32_t*>(&a);
    u.y = *reinterpret_cast<uint32_t*>(&b);
    ((uint2*)dst)[off] = u;
}

// ------- reduce SPLITS fp32 partials -> bf16 ---------------------------------
__global__ __launch_bounds__(256) void reduce_bf16(
    const float* __restrict__ part, __nv_bfloat16* __restrict__ out,
    int n4, int stride4)
{
    int i = blockIdx.x * blockDim.x + threadIdx.x;
    if (i >= n4) return;
    float4 s = ((const float4*)part)[i];
    #pragma unroll
    for (int sp = 1; sp < SPLITS; ++sp) {
        float4 v = ((const float4*)part)[i + sp * stride4];
        s.x += v.x; s.y += v.y; s.z += v.z; s.w += v.w;
    }
    __nv_bfloat162 a = __floats2bfloat162_rn(s.x, s.y);
    __nv_bfloat162 b = __floats2bfloat162_rn(s.z, s.w);
    uint2 u;
    u.x = *reinterpret_cast<uint32_t*>(&a);
    u.y = *reinterpret_cast<uint32_t*>(&b);
    ((uint2*)out)[i] = u;
}

// ------- softmax: sum SPLITS S-partials, *1/32, softmax, *prior -> bf16 ------
__global__ __launch_bounds__(256) void softmax_bf16(
    const float* __restrict__ Sp, const float* __restrict__ prior,
    __nv_bfloat16* __restrict__ A)
{
    const int STR4 = BB * KK / 4;   // float4 stride between splits
    int w = threadIdx.x >> 5, lid = threadIdx.x & 31;
    int row = blockIdx.x * 8 + w;
    int base4 = row * (KK / 4);
    float4 v0 = ((const float4*)Sp)[base4 + lid];
    float4 v1 = ((const float4*)Sp)[base4 + lid + 32];
    #pragma unroll
    for (int sp = 1; sp < SPLITS; ++sp) {
        float4 a = ((const float4*)Sp)[base4 + lid + sp * STR4];
        float4 b = ((const float4*)Sp)[base4 + lid + 32 + sp * STR4];
        v0.x += a.x; v0.y += a.y; v0.z += a.z; v0.w += a.w;
        v1.x += b.x; v1.y += b.y; v1.z += b.z; v1.w += b.w;
    }
    const float alpha = 0.03125f;
    float e[8] = {v0.x * alpha, v0.y * alpha, v0.z * alpha, v0.w * alpha,
                  v1.x * alpha, v1.y * alpha, v1.z * alpha, v1.w * alpha};
    float mx = e[0];
    #pragma unroll
    for (int i = 1; i < 8; i++) mx = fmaxf(mx, e[i]);
    #pragma unroll
    for (int o = 16; o; o >>= 1) mx = fmaxf(mx, __shfl_xor_sync(~0u, mx, o));
    float s = 0.f;
    #pragma unroll
    for (int i = 0; i < 8; i++) { e[i] = __expf(e[i] - mx); s += e[i]; }
    #pragma unroll
    for (int o = 16; o; o >>= 1) s += __shfl_xor_sync(~0u, s, o);
    float inv = 1.0f / s;
    float4 p0 = ((const float4*)prior)[lid];
    float4 p1 = ((const float4*)prior)[lid + 32];
    __nv_bfloat162 b01 = __floats2bfloat162_rn(e[0] * inv * p0.x, e[1] * inv * p0.y);
    __nv_bfloat162 b23 = __floats2bfloat162_rn(e[2] * inv * p0.z, e[3] * inv * p0.w);
    __nv_bfloat162 b45 = __floats2bfloat162_rn(e[4] * inv * p1.x, e[5] * inv * p1.y);
    __nv_bfloat162 b67 = __floats2bfloat162_rn(e[6] * inv * p1.z, e[7] * inv * p1.w);
    uint2 lo = make_uint2(*reinterpret_cast<uint32_t*>(&b01), *reinterpret_cast<uint32_t*>(&b23));
    uint2 hi = make_uint2(*reinterpret_cast<uint32_t*>(&b45), *reinterpret_cast<uint32_t*>(&b67));
    *(uint2*)(A + (size_t)row * KK + lid * 4)       = lo;
    *(uint2*)(A + (size_t)row * KK + 128 + lid * 4) = hi;
}

// ---------------- HMMA GEMM core (64x64 tile, 8 warps, warp 32x16, BK=64) ---
#define TM 64
#define TN 64
#define TKB 128
#define A_BYTES (TM * TKB)
#define STAGE_BYTES (2 * A_BYTES)

// SPLIT: K partitioned by blockIdx.z (Kc per split); fp32 partials at
// Cout + z*M*N. Non-split MODE 2 = f32 out + resid (G4).
template <int BNN, int SPLIT, int MODE>
__global__ __launch_bounds__(256, 3) void gemm_hmma(
    const __nv_bfloat16* __restrict__ A, const __nv_bfloat16* __restrict__ B,
    void* __restrict__ Cout, const float* __restrict__ resid,
    int Ntot, int Mtot, int K, int Kc)
{
    extern __shared__ char dsm_raw[];
    char* dsm = (char*)(((uintptr_t)dsm_raw + 1023) & ~(uintptr_t)1023);
    const uint32_t smem_base = smem_u32(dsm);

    const int tid = threadIdx.x;
    const int wid = tid >> 5;
    const int lid = tid & 31;
    const int wm = (wid >> 2) * 32;     // warp row: 2 warp-rows of 32
    const int wn = (wid & 3) * 16;      // warp col: 4 warp-cols of 16

    const int row0 = blockIdx.y * TM;
    const int col0 = blockIdx.x * TN;
    const int Koff = SPLIT ? blockIdx.z * Kc : 0;
    const int nk = (SPLIT ? Kc : K) >> 6;

    const char* Abase = (const char*)A;
    const char* Bbase = (const char*)B;

    float acc[2][2][4] = {};   // mi (2x16 rows) x ni (2x8 cols)

    auto load_stage = [&](int s, int it) {
        const uint32_t sA = smem_base + s * STAGE_BYTES;
        const uint32_t sB = sA + A_BYTES;
        #pragma unroll
        for (int i = 0; i < 2; i++) {
            int ci = tid + i * 256;           // 0..511
            int r = ci >> 3, c16 = ci & 7;
            size_t gb = ((size_t)(row0 + r) * K + Koff + it * 64) * 2 + c16 * 16;
            uint32_t off = r * TKB + c16 * 16;
            cp_async16(sA + sw128(off), Abase + gb);
        }
        #pragma unroll
        for (int i = 0; i < 2; i++) {
            int ci = tid + i * 256;
            int r = ci >> 3, c16 = ci & 7;
            size_t gb;
            if (BNN)
                gb = ((size_t)(Koff + it * 64 + r) * Ntot + col0) * 2 + c16 * 16;
            else
                gb = ((size_t)(col0 + r) * K + Koff + it * 64) * 2 + c16 * 16;
            uint32_t off = r * TKB + c16 * 16;
            cp_async16(sB + sw128(off), Bbase + gb);
        }
        cp_commit();
    };

    load_stage(0, 0);

    for (int it = 0; it < nk; ++it) {
        if (it + 1 < nk) { load_stage((it + 1) & 1, it + 1); cp_wait1(); }
        else             { cp_wait0(); }
        __syncthreads();

        const uint32_t sA = smem_base + (it & 1) * STAGE_BYTES;
        const uint32_t sB = sA + A_BYTES;

        #pragma unroll
        for (int ks = 0; ks < 4; ++ks) {
            uint32_t afr[2][4], bfr[4];
            #pragma unroll
            for (int mi = 0; mi < 2; ++mi) {
                int row = wm + mi * 16 + (lid & 15);
                uint32_t off = row * TKB + ks * 32 + (lid >> 4) * 16;
                ldmatrix_x4(afr[mi], sA + sw128(off));
            }
            if (BNN) {
                // B tile [k=64 rows][n=64 cols]; 16x16 (k,n) chunk at (ks*16, wn)
                int k = ks * 16 + ((lid >> 3) & 1) * 8 + (lid & 7);
                int n = wn + (lid >> 4) * 8;
                uint32_t off = k * TKB + n * 2;
                ldmatrix_x4_trans(bfr, sB + sw128(off));
            } else {
                // B tile [n=64 rows][k=64 cols]; rows wn..wn+15, k-chunk ks
                int row = wn + ((lid >> 4) << 3) + (lid & 7);
                uint32_t off = row * TKB + ks * 32 + ((lid >> 3) & 1) * 16;
                ldmatrix_x4(bfr, sB + sw128(off));
            }
            #pragma unroll
            for (int mi = 0; mi < 2; ++mi)
                #pragma unroll
                for (int ni = 0; ni < 2; ++ni)
                    mma_bf16(acc[mi][ni], afr[mi], bfr[ni * 2], bfr[ni * 2 + 1]);
        }
        __syncthreads();
    }

    const int group = lid >> 2;
    const int tc = (lid & 3) * 2;
    float* opart = (float*)Cout + (SPLIT ? (size_t)blockIdx.z * Mtot * Ntot : 0);
    #pragma unroll
    for (int mi = 0; mi < 2; ++mi) {
        #pragma unroll
        for (int ni = 0; ni < 2; ++ni) {
            int r = row0 + wm + mi * 16 + group;
            int c = col0 + wn + ni * 8 + tc;
            float* cc = acc[mi][ni];
            if (SPLIT) {
                *(float2*)(opart + (size_t)r * Ntot + c) = make_float2(cc[0], cc[1]);
                *(float2*)(opart + (size_t)(r + 8) * Ntot + c) = make_float2(cc[2], cc[3]);
            } else if (MODE == 2) {
                float* o = (float*)Cout;
                float2 j0 = *(const float2*)(resid + (size_t)r * Ntot + c);
                float2 j1 = *(const float2*)(resid + (size_t)(r + 8) * Ntot + c);
                *(float2*)(o + (size_t)r * Ntot + c) = make_float2(cc[0] + j0.x, cc[1] + j0.y);
                *(float2*)(o + (size_t)(r + 8) * Ntot + c) = make_float2(cc[2] + j1.x, cc[3] + j1.y);
            }
        }
    }
}

// ---------------- host ------------------------------------------------------
extern "C" void kernel_launch(void* const* d_in, const int* in_sizes, int n_in,
                              void* d_out, int out_size)
{
    const float* joint = (const float*)d_in[0];
    const float* conf  = (const float*)d_in[1];
    const float* prior = (const float*)d_in[2];
    const float* Wq    = (const float*)d_in[3];
    const float* Wk    = (const float*)d_in[4];
    float* out = (float*)d_out;

    __nv_bfloat16 *joint_bf, *conf_bf, *Wq_bf, *Wk_bf, *Kmat_bf, *W2T_bf, *attn_bf;
    float* part;
    cudaGetSymbolAddress((void**)&joint_bf, g_joint_bf);
    cudaGetSymbolAddress((void**)&conf_bf,  g_conf_bf);
    cudaGetSymbolAddress((void**)&Wq_bf,    g_Wq_bf);
    cudaGetSymbolAddress((void**)&Wk_bf,    g_Wk_bf);
    cudaGetSymbolAddress((void**)&Kmat_bf,  g_Kmat_bf);
    cudaGetSymbolAddress((void**)&W2T_bf,   g_W2T_bf);
    cudaGetSymbolAddress((void**)&attn_bf,  g_attn_bf);
    cudaGetSymbolAddress((void**)&part,     g_part);

    const int smem_bytes = 2 * STAGE_BYTES + 1024;   // 33 KB
    cudaFuncSetAttribute((const void*)gemm_hmma<1, 1, 0>, cudaFuncAttributeMaxDynamicSharedMemorySize, smem_bytes);
    cudaFuncSetAttribute((const void*)gemm_hmma<0, 1, 0>, cudaFuncAttributeMaxDynamicSharedMemorySize, smem_bytes);
    cudaFuncSetAttribute((const void*)gemm_hmma<1, 0, 2>, cudaFuncAttributeMaxDynamicSharedMemorySize, smem_bytes);

    // fused conversions
    conv_all<<<(N4_TOTAL + 255) / 256, 256>>>(joint, conf, Wq, Wk,
                                              joint_bf, conf_bf, Wq_bf, Wk_bf);
    // G1 (NN, split-K 4): part = conf_bf @ Wk_bf  (K=1024, Kc=256) -> 192 CTAs
    gemm_hmma<1, 1, 0><<<dim3(PP / TN, KK / TM, SPLITS), 256, smem_bytes>>>(
        conf_bf, Wk_bf, part, nullptr, PP, KK, DD, DD / SPLITS);
    reduce_bf16<<<(KK * PP / 4 + 255) / 256, 256>>>(part, Kmat_bf, KK * PP / 4,
                                                    KK * PP / 4);
    // G2 (NT, split-K 4): part = Kmat @ Wq_bf^T  (K=768, Kc=192) -> 256 CTAs
    gemm_hmma<0, 1, 0><<<dim3(DD / TN, KK / TM, SPLITS), 256, smem_bytes>>>(
        Kmat_bf, Wq_bf, part, nullptr, DD, KK, PP, PP / SPLITS);
    reduce_bf16<<<(KK * DD / 4 + 255) / 256, 256>>>(part, W2T_bf, KK * DD / 4,
                                                    KK * DD / 4);
    // G3 (NT, split-K 4): part = joint_bf @ W2T^T  (K=1024, Kc=256) -> 256 CTAs
    gemm_hmma<0, 1, 0><<<dim3(KK / TN, BB / TM, SPLITS), 256, smem_bytes>>>(
        joint_bf, W2T_bf, part, nullptr, KK, BB, DD, DD / SPLITS);
    // softmax: fused 4-way partial reduce + *1/32 + softmax + *prior -> attn
    softmax_bf16<<<BB / 8, 256>>>(part, prior, attn_bf);
    // G4 (NN): out = attn_bf @ conf_bf + joint  (K=256) -> 256 CTAs
    gemm_hmma<1, 0, 2><<<dim3(DD / TN, BB / TM, 1), 256, smem_bytes>>>(
        attn_bf, conf_bf, out, joint, DD, BB, KK, KK);
}

// round 16
// speedup vs baseline: 1.3828x; 1.0982x over previous
#include <cuda_runtime.h>
#include <cuda_bf16.h>
#include <cstdint>

// Shapes (fixed): joint [B=1024, D=1024], conf [K=256, D=1024], prior [K,1],
// Wq [D, P=768], Wk [D, P=768], out [B, D]. All fp32 in global.
//
// Dataflow (bf16 HMMA mma.sync, fp32 accum; split-K = 4 on skinny GEMMs):
//   conv:  joint_bf, conf_bf, Wq_bf, Wk_bf        (one fused kernel)
//   G1(NN, splitK=4): part = conf_bf @ Wk_bf      (K=1024,Kc=256) -> fp32 partials
//        reduce(4) -> Kmat_bf [256,768]
//   G2(NT, splitK=4): part = Kmat @ Wq_bf^T       (K=768, Kc=192) -> fp32 partials
//        reduce(4) -> W2T_bf [256,1024]
//   G3(NT, splitK=4): part = joint_bf @ W2T^T     (K=1024,Kc=256) -> fp32 partials
//   softmax (fused: sum 4 partials, *1/32, softmax, *prior) -> attn_bf [1024,256]
//   G4(NN): out = attn_bf @ conf_bf + joint       (K=256)  -> f32
//
// GEMM core: 64x64 CTA tile, 4 warps (2x2, 32x32 each), BK=64,
// THREE-stage cp.async pipeline (2 stages of lookahead to hide L2 latency).

#define BB 1024
#define KK 256
#define DD 1024
#define PP 768
#define SPLITS 4

// ---------------- scratch (device globals; no allocation allowed) ----------
__device__ __align__(16) __nv_bfloat16 g_joint_bf[BB * DD];
__device__ __align__(16) __nv_bfloat16 g_conf_bf[KK * DD];
__device__ __align__(16) __nv_bfloat16 g_Wq_bf[DD * PP];
__device__ __align__(16) __nv_bfloat16 g_Wk_bf[DD * PP];
__device__ __align__(16) __nv_bfloat16 g_Kmat_bf[KK * PP];
__device__ __align__(16) __nv_bfloat16 g_W2T_bf[KK * DD];
__device__ __align__(16) __nv_bfloat16 g_attn_bf[BB * KK];
__device__ __align__(16) float         g_part[SPLITS * BB * KK];  // 4 MB, reused

// ---------------- baseline-PTX helpers --------------------------------------
__device__ __forceinline__ uint32_t smem_u32(const void* p) {
    uint32_t a;
    asm("{ .reg .u64 t; cvta.to.shared.u64 t, %1; cvt.u32.u64 %0, t; }"
        : "=r"(a) : "l"(p));
    return a;
}
__device__ __forceinline__ void cp_async16(uint32_t dst, const void* src) {
    asm volatile("cp.async.cg.shared.global [%0], [%1], 16;"
                 :: "r"(dst), "l"(src) : "memory");
}
__device__ __forceinline__ void cp_commit() {
    asm volatile("cp.async.commit_group;" ::: "memory");
}
__device__ __forceinline__ void cp_wait2() {
    asm volatile("cp.async.wait_group 2;" ::: "memory");
}
__device__ __forceinline__ void cp_wait1() {
    asm volatile("cp.async.wait_group 1;" ::: "memory");
}
__device__ __forceinline__ void cp_wait0() {
    asm volatile("cp.async.wait_group 0;" ::: "memory");
}
__device__ __forceinline__ void ldmatrix_x4(uint32_t* r, uint32_t addr) {
    asm volatile("ldmatrix.sync.aligned.m8n8.x4.shared.b16 {%0,%1,%2,%3}, [%4];"
                 : "=r"(r[0]), "=r"(r[1]), "=r"(r[2]), "=r"(r[3]) : "r"(addr));
}
__device__ __forceinline__ void ldmatrix_x4_trans(uint32_t* r, uint32_t addr) {
    asm volatile("ldmatrix.sync.aligned.m8n8.x4.trans.shared.b16 {%0,%1,%2,%3}, [%4];"
                 : "=r"(r[0]), "=r"(r[1]), "=r"(r[2]), "=r"(r[3]) : "r"(addr));
}
__device__ __forceinline__ void mma_bf16(float* c, const uint32_t* a,
                                         uint32_t b0, uint32_t b1) {
    asm volatile(
        "mma.sync.aligned.m16n8k16.row.col.f32.bf16.bf16.f32 "
        "{%0,%1,%2,%3}, {%4,%5,%6,%7}, {%8,%9}, {%0,%1,%2,%3};"
        : "+f"(c[0]), "+f"(c[1]), "+f"(c[2]), "+f"(c[3])
        : "r"(a[0]), "r"(a[1]), "r"(a[2]), "r"(a[3]), "r"(b0), "r"(b1));
}
__device__ __forceinline__ uint32_t sw128(uint32_t off) {
    return off ^ ((off >> 3) & 0x70);
}

// ---------------- fused fp32 -> bf16 conversion (all 4 inputs) --------------
#define N4_JOINT  (BB * DD / 4)
#define N4_CONF   (KK * DD / 4)
#define N4_W      (DD * PP / 4)
#define N4_TOTAL  (N4_JOINT + N4_CONF + 2 * N4_W)

__global__ __launch_bounds__(256) void conv_all(
    const float* __restrict__ joint, const float* __restrict__ conf,
    const float* __restrict__ wq, const float* __restrict__ wk,
    __nv_bfloat16* __restrict__ jb, __nv_bfloat16* __restrict__ cb,
    __nv_bfloat16* __restrict__ qb, __nv_bfloat16* __restrict__ kb)
{
    int i = blockIdx.x * blockDim.x + threadIdx.x;
    const float* src;
    __nv_bfloat16* dst;
    int off;
    if (i < N4_JOINT)                       { src = joint; dst = jb; off = i; }
    else if (i < N4_JOINT + N4_CONF)        { src = conf;  dst = cb; off = i - N4_JOINT; }
    else if (i < N4_JOINT + N4_CONF + N4_W) { src = wq;    dst = qb; off = i - N4_JOINT - N4_CONF; }
    else if (i < N4_TOTAL)                  { src = wk;    dst = kb; off = i - N4_JOINT - N4_CONF - N4_W; }
    else return;
    float4 v = ((const float4*)src)[off];
    __nv_bfloat162 a = __floats2bfloat162_rn(v.x, v.y);
    __nv_bfloat162 b = __floats2bfloat162_rn(v.z, v.w);
    uint2 u;
    u.x = *reinterpret_cast<uint32_t*>(&a);
    u.y = *reinterpret_cast<uint32_t*>(&b);
    ((uint2*)dst)[off] = u;
}

// ------- reduce SPLITS fp32 partials -> bf16 ---------------------------------
__global__ __launch_bounds__(256) void reduce_bf16(
    const float* __restrict__ part, __nv_bfloat16* __restrict__ out,
    int n4, int stride4)
{
    int i = blockIdx.x * blockDim.x + threadIdx.x;
    if (i >= n4) return;
    float4 s = ((const float4*)part)[i];
    #pragma unroll
    for (int sp = 1; sp < SPLITS; ++sp) {
        float4 v = ((const float4*)part)[i + sp * stride4];
        s.x += v.x; s.y += v.y; s.z += v.z; s.w += v.w;
    }
    __nv_bfloat162 a = __floats2bfloat162_rn(s.x, s.y);
    __nv_bfloat162 b = __floats2bfloat162_rn(s.z, s.w);
    uint2 u;
    u.x = *reinterpret_cast<uint32_t*>(&a);
    u.y = *reinterpret_cast<uint32_t*>(&b);
    ((uint2*)out)[i] = u;
}

// ------- softmax: sum SPLITS S-partials, *1/32, softmax, *prior -> bf16 ------
__global__ __launch_bounds__(256) void softmax_bf16(
    const float* __restrict__ Sp, const float* __restrict__ prior,
    __nv_bfloat16* __restrict__ A)
{
    const int STR4 = BB * KK / 4;   // float4 stride between splits
    int w = threadIdx.x >> 5, lid = threadIdx.x & 31;
    int row = blockIdx.x * 8 + w;
    int base4 = row * (KK / 4);
    float4 v0 = ((const float4*)Sp)[base4 + lid];
    float4 v1 = ((const float4*)Sp)[base4 + lid + 32];
    #pragma unroll
    for (int sp = 1; sp < SPLITS; ++sp) {
        float4 a = ((const float4*)Sp)[base4 + lid + sp * STR4];
        float4 b = ((const float4*)Sp)[base4 + lid + 32 + sp * STR4];
        v0.x += a.x; v0.y += a.y; v0.z += a.z; v0.w += a.w;
        v1.x += b.x; v1.y += b.y; v1.z += b.z; v1.w += b.w;
    }
    const float alpha = 0.03125f;
    float e[8] = {v0.x * alpha, v0.y * alpha, v0.z * alpha, v0.w * alpha,
                  v1.x * alpha, v1.y * alpha, v1.z * alpha, v1.w * alpha};
    float mx = e[0];
    #pragma unroll
    for (int i = 1; i < 8; i++) mx = fmaxf(mx, e[i]);
    #pragma unroll
    for (int o = 16; o; o >>= 1) mx = fmaxf(mx, __shfl_xor_sync(~0u, mx, o));
    float s = 0.f;
    #pragma unroll
    for (int i = 0; i < 8; i++) { e[i] = __expf(e[i] - mx); s += e[i]; }
    #pragma unroll
    for (int o = 16; o; o >>= 1) s += __shfl_xor_sync(~0u, s, o);
    float inv = 1.0f / s;
    float4 p0 = ((const float4*)prior)[lid];
    float4 p1 = ((const float4*)prior)[lid + 32];
    __nv_bfloat162 b01 = __floats2bfloat162_rn(e[0] * inv * p0.x, e[1] * inv * p0.y);
    __nv_bfloat162 b23 = __floats2bfloat162_rn(e[2] * inv * p0.z, e[3] * inv * p0.w);
    __nv_bfloat162 b45 = __floats2bfloat162_rn(e[4] * inv * p1.x, e[5] * inv * p1.y);
    __nv_bfloat162 b67 = __floats2bfloat162_rn(e[6] * inv * p1.z, e[7] * inv * p1.w);
    uint2 lo = make_uint2(*reinterpret_cast<uint32_t*>(&b01), *reinterpret_cast<uint32_t*>(&b23));
    uint2 hi = make_uint2(*reinterpret_cast<uint32_t*>(&b45), *reinterpret_cast<uint32_t*>(&b67));
    *(uint2*)(A + (size_t)row * KK + lid * 4)       = lo;
    *(uint2*)(A + (size_t)row * KK + 128 + lid * 4) = hi;
}

// ---------------- HMMA GEMM core (64x64 tile, 4 warps, BK=64, 3 stages) -----
#define TM 64
#define TN 64
#define TKB 128
#define A_BYTES (TM * TKB)
#define STAGE_BYTES (2 * A_BYTES)     // 16 KB (A then B)
#define NSTAGE 3

// SPLIT: K partitioned by blockIdx.z (Kc per split); fp32 partials at
// Cout + z*M*N. Non-split MODE 2 = f32 out + resid (G4).
template <int BNN, int SPLIT, int MODE>
__global__ __launch_bounds__(128, 4) void gemm_hmma(
    const __nv_bfloat16* __restrict__ A, const __nv_bfloat16* __restrict__ B,
    void* __restrict__ Cout, const float* __restrict__ resid,
    int Ntot, int Mtot, int K, int Kc)
{
    extern __shared__ char dsm_raw[];
    char* dsm = (char*)(((uintptr_t)dsm_raw + 1023) & ~(uintptr_t)1023);
    const uint32_t smem_base = smem_u32(dsm);

    const int tid = threadIdx.x;
    const int wid = tid >> 5;
    const int lid = tid & 31;
    const int wm = (wid >> 1) * 32;
    const int wn = (wid & 1) * 32;

    const int row0 = blockIdx.y * TM;
    const int col0 = blockIdx.x * TN;
    const int Koff = SPLIT ? blockIdx.z * Kc : 0;
    const int nk = (SPLIT ? Kc : K) >> 6;

    const char* Abase = (const char*)A;
    const char* Bbase = (const char*)B;

    float acc[2][4][4] = {};

    auto load_stage = [&](int s, int it) {
        const uint32_t sA = smem_base + s * STAGE_BYTES;
        const uint32_t sB = sA + A_BYTES;
        #pragma unroll
        for (int i = 0; i < 4; i++) {
            int ci = tid + i * 128;
            int r = ci >> 3, c16 = ci & 7;
            size_t gb = ((size_t)(row0 + r) * K + Koff + it * 64) * 2 + c16 * 16;
            uint32_t off = r * TKB + c16 * 16;
            cp_async16(sA + sw128(off), Abase + gb);
        }
        #pragma unroll
        for (int i = 0; i < 4; i++) {
            int ci = tid + i * 128;
            int r = ci >> 3, c16 = ci & 7;
            size_t gb;
            if (BNN)
                gb = ((size_t)(Koff + it * 64 + r) * Ntot + col0) * 2 + c16 * 16;
            else
                gb = ((size_t)(col0 + r) * K + Koff + it * 64) * 2 + c16 * 16;
            uint32_t off = r * TKB + c16 * 16;
            cp_async16(sB + sw128(off), Bbase + gb);
        }
        cp_commit();
    };

    // Prologue: 2 stages of lookahead.
    load_stage(0, 0);
    if (nk > 1) load_stage(1, 1);

    int stage = 0;
    for (int it = 0; it < nk; ++it) {
        // Issue it+2, then wait until stage `it` is resident.
        if (it + 2 < nk) {
            load_stage((stage + 2) % NSTAGE, it + 2);
            cp_wait2();
        } else if (it + 1 < nk) {
            cp_wait1();
        } else {
            cp_wait0();
        }
        __syncthreads();

        const uint32_t sA = smem_base + stage * STAGE_BYTES;
        const uint32_t sB = sA + A_BYTES;

        #pragma unroll
        for (int ks = 0; ks < 4; ++ks) {
            uint32_t afr[2][4], bfr[2][4];
            #pragma unroll
            for (int mi = 0; mi < 2; ++mi) {
                int row = wm + mi * 16 + (lid & 15);
                uint32_t off = row * TKB + ks * 32 + (lid >> 4) * 16;
                ldmatrix_x4(afr[mi], sA + sw128(off));
            }
            #pragma unroll
            for (int np = 0; np < 2; ++np) {
                if (BNN) {
                    int k = ks * 16 + ((lid >> 3) & 1) * 8 + (lid & 7);
                    int n = wn + np * 16 + (lid >> 4) * 8;
                    uint32_t off = k * TKB + n * 2;
                    ldmatrix_x4_trans(bfr[np], sB + sw128(off));
                } else {
                    int row = wn + np * 16 + ((lid >> 4) << 3) + (lid & 7);
                    uint32_t off = row * TKB + ks * 32 + ((lid >> 3) & 1) * 16;
                    ldmatrix_x4(bfr[np], sB + sw128(off));
                }
            }
            #pragma unroll
            for (int mi = 0; mi < 2; ++mi)
                #pragma unroll
                for (int ni = 0; ni < 4; ++ni)
                    mma_bf16(acc[mi][ni], afr[mi],
                             bfr[ni >> 1][(ni & 1) * 2],
                             bfr[ni >> 1][(ni & 1) * 2 + 1]);
        }
        __syncthreads();
        stage = (stage + 1) % NSTAGE;
    }

    const int group = lid >> 2;
    const int tc = (lid & 3) * 2;
    float* opart = (float*)Cout + (SPLIT ? (size_t)blockIdx.z * Mtot * Ntot : 0);
    #pragma unroll
    for (int mi = 0; mi < 2; ++mi) {
        #pragma unroll
        for (int ni = 0; ni < 4; ++ni) {
            int r = row0 + wm + mi * 16 + group;
            int c = col0 + wn + ni * 8 + tc;
            float* cc = acc[mi][ni];
            if (SPLIT) {
                *(float2*)(opart + (size_t)r * Ntot + c) = make_float2(cc[0], cc[1]);
                *(float2*)(opart + (size_t)(r + 8) * Ntot + c) = make_float2(cc[2], cc[3]);
            } else if (MODE == 2) {
                float* o = (float*)Cout;
                float2 j0 = *(const float2*)(resid + (size_t)r * Ntot + c);
                float2 j1 = *(const float2*)(resid + (size_t)(r + 8) * Ntot + c);
                *(float2*)(o + (size_t)r * Ntot + c) = make_float2(cc[0] + j0.x, cc[1] + j0.y);
                *(float2*)(o + (size_t)(r + 8) * Ntot + c) = make_float2(cc[2] + j1.x, cc[3] + j1.y);
            }
        }
    }
}

// ---------------- host ------------------------------------------------------
extern "C" void kernel_launch(void* const* d_in, const int* in_sizes, int n_in,
                              void* d_out, int out_size)
{
    const float* joint = (const float*)d_in[0];
    const float* conf  = (const float*)d_in[1];
    const float* prior = (const float*)d_in[2];
    const float* Wq    = (const float*)d_in[3];
    const float* Wk    = (const float*)d_in[4];
    float* out = (float*)d_out;

    __nv_bfloat16 *joint_bf, *conf_bf, *Wq_bf, *Wk_bf, *Kmat_bf, *W2T_bf, *attn_bf;
    float* part;
    cudaGetSymbolAddress((void**)&joint_bf, g_joint_bf);
    cudaGetSymbolAddress((void**)&conf_bf,  g_conf_bf);
    cudaGetSymbolAddress((void**)&Wq_bf,    g_Wq_bf);
    cudaGetSymbolAddress((void**)&Wk_bf,    g_Wk_bf);
    cudaGetSymbolAddress((void**)&Kmat_bf,  g_Kmat_bf);
    cudaGetSymbolAddress((void**)&W2T_bf,   g_W2T_bf);
    cudaGetSymbolAddress((void**)&attn_bf,  g_attn_bf);
    cudaGetSymbolAddress((void**)&part,     g_part);

    const int smem_bytes = NSTAGE * STAGE_BYTES + 1024;   // 49 KB
    cudaFuncSetAttribute((const void*)gemm_hmma<1, 1, 0>, cudaFuncAttributeMaxDynamicSharedMemorySize, smem_bytes);
    cudaFuncSetAttribute((const void*)gemm_hmma<0, 1, 0>, cudaFuncAttributeMaxDynamicSharedMemorySize, smem_bytes);
    cudaFuncSetAttribute((const void*)gemm_hmma<1, 0, 2>, cudaFuncAttributeMaxDynamicSharedMemorySize, smem_bytes);

    // fused conversions
    conv_all<<<(N4_TOTAL + 255) / 256, 256>>>(joint, conf, Wq, Wk,
                                              joint_bf, conf_bf, Wq_bf, Wk_bf);
    // G1 (NN, split-K 4): part = conf_bf @ Wk_bf  (K=1024, Kc=256) -> 192 CTAs
    gemm_hmma<1, 1, 0><<<dim3(PP / TN, KK / TM, SPLITS), 128, smem_bytes>>>(
        conf_bf, Wk_bf, part, nullptr, PP, KK, DD, DD / SPLITS);
    reduce_bf16<<<(KK * PP / 4 + 255) / 256, 256>>>(part, Kmat_bf, KK * PP / 4,
                                                    KK * PP / 4);
    // G2 (NT, split-K 4): part = Kmat @ Wq_bf^T  (K=768, Kc=192) -> 256 CTAs
    gemm_hmma<0, 1, 0><<<dim3(DD / TN, KK / TM, SPLITS), 128, smem_bytes>>>(
        Kmat_bf, Wq_bf, part, nullptr, DD, KK, PP, PP / SPLITS);
    reduce_bf16<<<(KK * DD / 4 + 255) / 256, 256>>>(part, W2T_bf, KK * DD / 4,
                                                    KK * DD / 4);
    // G3 (NT, split-K 4): part = joint_bf @ W2T^T  (K=1024, Kc=256) -> 256 CTAs
    gemm_hmma<0, 1, 0><<<dim3(KK / TN, BB / TM, SPLITS), 128, smem_bytes>>>(
        joint_bf, W2T_bf, part, nullptr, KK, BB, DD, DD / SPLITS);
    // softmax: fused 4-way partial reduce + *1/32 + softmax + *prior -> attn
    softmax_bf16<<<BB / 8, 256>>>(part, prior, attn_bf);
    // G4 (NN): out = attn_bf @ conf_bf + joint  (K=256) -> 256 CTAs
    gemm_hmma<1, 0, 2><<<dim3(DD / TN, BB / TM, 1), 128, smem_bytes>>>(
        attn_bf, conf_bf, out, joint, DD, BB, KK, KK);
}